// round 9
// baseline (speedup 1.0000x reference)
#include <cuda_runtime.h>
#include <cstdint>

// Problem shape (fixed for this dataset entry)
#define B_ 4
#define C_ 32
#define H_ 256
#define W_ 512
#define D_ 48

#define WT   128            // w-tile per block
#define TW   (WT + D_)      // 176: h1 tile width, mult of 4 -> rows 16B-aligned, no pad
#define NTHREADS 256
#define CH_T 4              // channels per thread (warp wid owns 4*wid..4*wid+3)
#define W_T  4              // w outputs per thread (w0 = lane*4)
#define ROUNDS (D_ / 4)     // 12 rounds of 4 d-steps

typedef unsigned long long ull;

// --- packed f32x2 helpers (FFMA2 is PTX-only; ptxas never auto-fuses) ---
__device__ __forceinline__ void fma2(ull &acc, ull a, ull b) {
    asm("fma.rn.f32x2 %0, %1, %2, %0;" : "+l"(acc) : "l"(a), "l"(b));
}
__device__ __forceinline__ ull pack2(float lo, float hi) {
    ull r;
    asm("mov.b64 %0, {%1, %2};" : "=l"(r) : "f"(lo), "f"(hi));
    return r;
}
__device__ __forceinline__ void unpack2(ull a, float &lo, float &hi) {
    asm("mov.b64 {%0, %1}, %2;" : "=f"(lo), "=f"(hi) : "l"(a));
}

__global__ void __launch_bounds__(NTHREADS, 3)
dense_warp_kernel(const float* __restrict__ h1,
                  const float* __restrict__ cost,
                  float* __restrict__ out) {
    __shared__ __align__(16) float cost_s[D_ * WT];   // 24 KB
    __shared__ __align__(16) float h1_s[C_ * TW];     // 22 KB

    const int bx    = blockIdx.x;
    const int wt    = bx & 3;                 // W_/WT = 4 tiles
    const int h     = (bx >> 2) & (H_ - 1);
    const int b     = bx >> 10;               // /(4*256)
    const int wbase = wt * WT;
    const int tid   = threadIdx.x;

    // ---- load cost tile [D_ x WT] (float4, coalesced): 1536 float4 ----
    {
        const float* cbase = cost + ((size_t)(b * D_) * H_ + h) * W_ + wbase;
        #pragma unroll
        for (int it = 0; it < 6; it++) {
            int idx = it * NTHREADS + tid;
            int dd = idx >> 5;               // WT/4 = 32 float4 per row
            int ww = (idx & 31) << 2;
            *(float4*)&cost_s[dd * WT + ww] =
                *(const float4*)&cbase[(size_t)dd * (H_ * W_) + ww];
        }
    }
    // ---- load h1 tile [C_ x TW] (float4), zero-padded past W ----
    // boundary W - wbase is a multiple of 4 -> whole-float4 guard is exact
    {
        const float* hbase = h1 + ((size_t)(b * C_) * H_ + h) * W_ + wbase;
        for (int idx = tid; idx < C_ * (TW / 4); idx += NTHREADS) {  // 1408
            int cc = idx / (TW / 4);
            int x  = (idx - cc * (TW / 4)) * 4;
            float4 v = make_float4(0.0f, 0.0f, 0.0f, 0.0f);
            if (wbase + x < W_)
                v = *(const float4*)&hbase[(size_t)cc * (H_ * W_) + x];
            *(float4*)&h1_s[cc * TW + x] = v;
        }
    }
    __syncthreads();

    // lane spans w (fully distinct smem reads, 512B contiguous per warp);
    // warp wid owns channels {4*wid .. 4*wid+3}, kept in registers.
    const int lane  = tid & 31;
    const int wid   = tid >> 5;               // 0..7
    const int w0    = lane * 4;               // 0..124
    const int cbch  = wid * 4;

    const float* hr0 = &h1_s[cbch * TW + w0]; // +i*TW per channel
    const float* cb  = &cost_s[w0];

    // E-pair ring per channel: R holds even-aligned pairs of the sliding
    // window h1[w0+4t .. w0+4t+7].  Invariant at round t:
    //   R[(2t+k)&3] = (h1[w0+4t+2k], h1[w0+4t+2k+1]),  k=0..3
    ull R[CH_T][4], acc[CH_T][2];
    #pragma unroll
    for (int i = 0; i < CH_T; i++) {
        ulonglong2 a = *(const ulonglong2*)(hr0 + i * TW);      // x0..x3
        ulonglong2 c = *(const ulonglong2*)(hr0 + i * TW + 4);  // x4..x7
        R[i][0] = a.x; R[i][1] = a.y; R[i][2] = c.x; R[i][3] = c.y;
        acc[i][0] = 0ull; acc[i][1] = 0ull;
    }

    // 12 fully-unrolled rounds of 4 d-steps; static ring slots, immediate
    // smem offsets.  Per round per thread: 4 cost LDS.128 + CH_T refill
    // LDS.128 + 32 FFMA2 + 3*CH_T packs.
    #pragma unroll
    for (int t = 0; t < ROUNDS; t++) {
        ulonglong2 q0 = *(const ulonglong2*)(cb + (4 * t + 0) * WT);
        ulonglong2 q1 = *(const ulonglong2*)(cb + (4 * t + 1) * WT);
        ulonglong2 q2 = *(const ulonglong2*)(cb + (4 * t + 2) * WT);
        ulonglong2 q3 = *(const ulonglong2*)(cb + (4 * t + 3) * WT);

        #pragma unroll
        for (int i = 0; i < CH_T; i++) {
            ull E0 = R[i][(2 * t + 0) & 3], E1 = R[i][(2 * t + 1) & 3],
                E2 = R[i][(2 * t + 2) & 3], E3 = R[i][(2 * t + 3) & 3];

            // unpacks are register aliasing (free); packs are the only movs
            float x0, x1, x2, x3, x4, x5, x6, x7;
            unpack2(E0, x0, x1); unpack2(E1, x2, x3);
            unpack2(E2, x4, x5); unpack2(E3, x6, x7);
            ull O0 = pack2(x1, x2), O1 = pack2(x3, x4), O2 = pack2(x5, x6);

            // d = 4t   : pairs (x0,x1),(x2,x3) = E0,E1
            fma2(acc[i][0], q0.x, E0);  fma2(acc[i][1], q0.y, E1);
            // d = 4t+1 : pairs (x1,x2),(x3,x4) = O0,O1
            fma2(acc[i][0], q1.x, O0);  fma2(acc[i][1], q1.y, O1);
            // d = 4t+2 : pairs (x2,x3),(x4,x5) = E1,E2
            fma2(acc[i][0], q2.x, E1);  fma2(acc[i][1], q2.y, E2);
            // d = 4t+3 : pairs (x3,x4),(x5,x6) = O1,O2
            fma2(acc[i][0], q3.x, O1);  fma2(acc[i][1], q3.y, O2);

            // refill: two new even pairs (x8,x9),(x10,x11) land directly
            // in the ring slots freed this round (zero packing)
            if (t < ROUNDS - 1) {
                ulonglong2 nv =
                    *(const ulonglong2*)(hr0 + i * TW + 4 * t + 8);
                R[i][(2 * t + 0) & 3] = nv.x;
                R[i][(2 * t + 1) & 3] = nv.y;
            }
        }
    }

    // ---- store: 4 channels x 4 contiguous floats (1x STG.128 each);
    //      warp stores 512B contiguous per channel ----
    #pragma unroll
    for (int i = 0; i < CH_T; i++) {
        int c = cbch + i;
        float* orow = out + (((size_t)b * C_ + c) * H_ + h) * W_ + wbase + w0;
        *(ulonglong2*)orow = make_ulonglong2(acc[i][0], acc[i][1]);
    }
}

extern "C" void kernel_launch(void* const* d_in, const int* in_sizes, int n_in,
                              void* d_out, int out_size) {
    (void)in_sizes; (void)n_in; (void)out_size;
    const float* h1   = (const float*)d_in[0];
    const float* cost = (const float*)d_in[1];
    float* out        = (float*)d_out;

    const int nblocks = B_ * H_ * (W_ / WT);   // 4096
    dense_warp_kernel<<<nblocks, NTHREADS>>>(h1, cost, out);
}